// round 2
// baseline (speedup 1.0000x reference)
#include <cuda_runtime.h>
#include <cuda_bf16.h>

#define NNODES 50000
#define NEDGES 600000
#define C_IN   128
#define C_HID  128
#define C_OUT  40

// ---------------- scratch (static device globals; no allocation) -------------
__device__ float g_h1  [NNODES * C_HID];   // x@W1
__device__ float g_h1b [NNODES * C_HID];   // layer-1 output (post relu)
__device__ float g_h2  [NNODES * C_OUT];   // h1b@W2
__device__ float g_dinv[NNODES];
__device__ int   g_degi[NNODES];           // in-degree (excl self loop)
__device__ int   g_rowstart[NNODES + 1];
__device__ int   g_cursor[NNODES];
__device__ int   g_csr_src[NEDGES];
__device__ float g_csr_nrm[NEDGES];

// ---------------- zero int buffer --------------------------------------------
__global__ void zeroi_kernel(int* p, int n) {
    int i = blockIdx.x * blockDim.x + threadIdx.x;
    if (i < n) p[i] = 0;
}

// ---------------- degree + dinv ----------------------------------------------
__global__ void degree_kernel(const int* __restrict__ ei) {
    int e = blockIdx.x * blockDim.x + threadIdx.x;
    if (e < NEDGES) atomicAdd(&g_degi[ei[NEDGES + e]], 1);
}

__global__ void dinv_kernel() {
    int i = blockIdx.x * blockDim.x + threadIdx.x;
    if (i < NNODES) g_dinv[i] = rsqrtf((float)g_degi[i] + 1.0f);
}

// ---------------- one-block exclusive scan over 50k degrees ------------------
__global__ __launch_bounds__(1024) void scan_kernel() {
    __shared__ int sums[1024];
    const int CH = (NNODES + 1023) / 1024;   // 49
    int t = threadIdx.x;
    int base = t * CH;
    int local = 0;
#pragma unroll
    for (int i = 0; i < CH; i++) {
        int idx = base + i;
        if (idx < NNODES) local += g_degi[idx];
    }
    sums[t] = local;
    __syncthreads();
    // Hillis-Steele inclusive scan
    for (int off = 1; off < 1024; off <<= 1) {
        int v = 0;
        if (t >= off) v = sums[t - off];
        __syncthreads();
        if (t >= off) sums[t] += v;
        __syncthreads();
    }
    int run = (t == 0) ? 0 : sums[t - 1];
#pragma unroll
    for (int i = 0; i < CH; i++) {
        int idx = base + i;
        if (idx < NNODES) {
            g_rowstart[idx] = run;
            g_cursor[idx]   = run;
            run += g_degi[idx];
        }
    }
    if (t == 0) g_rowstart[NNODES] = NEDGES;
}

// ---------------- CSR fill: bucket edges by dst, precompute norms ------------
__global__ void csrfill_kernel(const int* __restrict__ ei) {
    int e = blockIdx.x * blockDim.x + threadIdx.x;
    if (e >= NEDGES) return;
    int s = ei[e];
    int d = ei[NEDGES + e];
    int pos = atomicAdd(&g_cursor[d], 1);
    g_csr_src[pos] = s;
    g_csr_nrm[pos] = g_dinv[s] * g_dinv[d];
}

// ---------------- GEMM: [M,128] @ [128,128] -> [M,128] -----------------------
__global__ __launch_bounds__(256) void gemm128_kernel(
    const float* __restrict__ A, const float* __restrict__ W,
    float* __restrict__ C, int M)
{
    __shared__ float xs[16][132];
    __shared__ float ws[16][128];

    int tid = threadIdx.x;
    int tx = tid & 15;
    int ty = tid >> 4;
    int r0 = blockIdx.x * 128;

    float acc[8][8];
#pragma unroll
    for (int i = 0; i < 8; i++)
#pragma unroll
        for (int j = 0; j < 8; j++) acc[i][j] = 0.f;

    for (int k0 = 0; k0 < 128; k0 += 16) {
#pragma unroll
        for (int L = tid; L < 512; L += 256) {
            int r  = L >> 2;
            int kg = L & 3;
            float4 v = make_float4(0.f, 0.f, 0.f, 0.f);
            int row = r0 + r;
            if (row < M)
                v = *(const float4*)&A[(size_t)row * 128 + k0 + kg * 4];
            xs[kg * 4 + 0][r] = v.x;
            xs[kg * 4 + 1][r] = v.y;
            xs[kg * 4 + 2][r] = v.z;
            xs[kg * 4 + 3][r] = v.w;
        }
#pragma unroll
        for (int L = tid; L < 512; L += 256) {
            int k  = L >> 5;
            int cg = L & 31;
            *(float4*)&ws[k][cg * 4] =
                *(const float4*)&W[(size_t)(k0 + k) * 128 + cg * 4];
        }
        __syncthreads();

#pragma unroll
        for (int k = 0; k < 16; ++k) {
            float a[8], b[8];
            *(float4*)(a)     = *(const float4*)&xs[k][ty * 8];
            *(float4*)(a + 4) = *(const float4*)&xs[k][ty * 8 + 4];
            *(float4*)(b)     = *(const float4*)&ws[k][tx * 8];
            *(float4*)(b + 4) = *(const float4*)&ws[k][tx * 8 + 4];
#pragma unroll
            for (int i = 0; i < 8; i++)
#pragma unroll
                for (int j = 0; j < 8; j++)
                    acc[i][j] = fmaf(a[i], b[j], acc[i][j]);
        }
        __syncthreads();
    }

#pragma unroll
    for (int i = 0; i < 8; i++) {
        int row = r0 + ty * 8 + i;
        if (row < M) {
            *(float4*)&C[(size_t)row * 128 + tx * 8] =
                make_float4(acc[i][0], acc[i][1], acc[i][2], acc[i][3]);
            *(float4*)&C[(size_t)row * 128 + tx * 8 + 4] =
                make_float4(acc[i][4], acc[i][5], acc[i][6], acc[i][7]);
        }
    }
}

// ---------------- GEMM: [M,128] @ [128,40] -> [M,40] -------------------------
__global__ __launch_bounds__(160) void gemm40_kernel(
    const float* __restrict__ A, const float* __restrict__ W,
    float* __restrict__ C, int M)
{
    __shared__ float xs[16][132];
    __shared__ float ws[16][40];

    int tid = threadIdx.x;
    int tx = tid % 10;
    int ty = tid / 10;
    int r0 = blockIdx.x * 128;

    float acc[8][4];
#pragma unroll
    for (int i = 0; i < 8; i++)
#pragma unroll
        for (int j = 0; j < 4; j++) acc[i][j] = 0.f;

    for (int k0 = 0; k0 < 128; k0 += 16) {
        for (int L = tid; L < 512; L += 160) {
            int r  = L >> 2;
            int kg = L & 3;
            float4 v = make_float4(0.f, 0.f, 0.f, 0.f);
            int row = r0 + r;
            if (row < M)
                v = *(const float4*)&A[(size_t)row * 128 + k0 + kg * 4];
            xs[kg * 4 + 0][r] = v.x;
            xs[kg * 4 + 1][r] = v.y;
            xs[kg * 4 + 2][r] = v.z;
            xs[kg * 4 + 3][r] = v.w;
        }
        {
            int L = tid;
            int k  = L / 10;
            int cg = L % 10;
            *(float4*)&ws[k][cg * 4] =
                *(const float4*)&W[(size_t)(k0 + k) * 40 + cg * 4];
        }
        __syncthreads();

#pragma unroll
        for (int k = 0; k < 16; ++k) {
            float a[8], b[4];
            *(float4*)(a)     = *(const float4*)&xs[k][ty * 8];
            *(float4*)(a + 4) = *(const float4*)&xs[k][ty * 8 + 4];
            *(float4*)(b)     = *(const float4*)&ws[k][tx * 4];
#pragma unroll
            for (int i = 0; i < 8; i++)
#pragma unroll
                for (int j = 0; j < 4; j++)
                    acc[i][j] = fmaf(a[i], b[j], acc[i][j]);
        }
        __syncthreads();
    }

#pragma unroll
    for (int i = 0; i < 8; i++) {
        int row = r0 + ty * 8 + i;
        if (row < M) {
            *(float4*)&C[(size_t)row * 40 + tx * 4] =
                make_float4(acc[i][0], acc[i][1], acc[i][2], acc[i][3]);
        }
    }
}

// ---------------- gather layer 1 (C=128): warp per node ----------------------
// acc = sum_j nrm_j * h1[src_j] ; out = relu(acc + dinv^2*h1[node] + b1)
__global__ __launch_bounds__(256) void gather128_kernel(const float* __restrict__ b1) {
    int w = (blockIdx.x * blockDim.x + threadIdx.x) >> 5;
    if (w >= NNODES) return;
    int lane = threadIdx.x & 31;

    int start = g_rowstart[w];
    int end   = g_rowstart[w + 1];

    const float4* __restrict__ h = (const float4*)g_h1;
    float4 acc = make_float4(0.f, 0.f, 0.f, 0.f);

    int j = start;
    for (; j + 1 < end; j += 2) {
        int   s0 = __ldg(&g_csr_src[j]);
        int   s1 = __ldg(&g_csr_src[j + 1]);
        float n0 = __ldg(&g_csr_nrm[j]);
        float n1 = __ldg(&g_csr_nrm[j + 1]);
        float4 v0 = h[(size_t)s0 * 32 + lane];
        float4 v1 = h[(size_t)s1 * 32 + lane];
        acc.x = fmaf(n0, v0.x, acc.x); acc.y = fmaf(n0, v0.y, acc.y);
        acc.z = fmaf(n0, v0.z, acc.z); acc.w = fmaf(n0, v0.w, acc.w);
        acc.x = fmaf(n1, v1.x, acc.x); acc.y = fmaf(n1, v1.y, acc.y);
        acc.z = fmaf(n1, v1.z, acc.z); acc.w = fmaf(n1, v1.w, acc.w);
    }
    if (j < end) {
        int   s0 = __ldg(&g_csr_src[j]);
        float n0 = __ldg(&g_csr_nrm[j]);
        float4 v0 = h[(size_t)s0 * 32 + lane];
        acc.x = fmaf(n0, v0.x, acc.x); acc.y = fmaf(n0, v0.y, acc.y);
        acc.z = fmaf(n0, v0.z, acc.z); acc.w = fmaf(n0, v0.w, acc.w);
    }

    float di = g_dinv[w];
    float d2 = di * di;
    float4 hv = h[(size_t)w * 32 + lane];
    float4 bb = ((const float4*)b1)[lane];
    float4 r;
    r.x = fmaxf(fmaf(hv.x, d2, acc.x) + bb.x, 0.f);
    r.y = fmaxf(fmaf(hv.y, d2, acc.y) + bb.y, 0.f);
    r.z = fmaxf(fmaf(hv.z, d2, acc.z) + bb.z, 0.f);
    r.w = fmaxf(fmaf(hv.w, d2, acc.w) + bb.w, 0.f);
    ((float4*)g_h1b)[(size_t)w * 32 + lane] = r;
}

// ---------------- gather layer 2 (C=40): warp per node, lanes 0-9 -----------
__global__ __launch_bounds__(256) void gather40_kernel(const float* __restrict__ b2,
                                                       float* __restrict__ out) {
    int w = (blockIdx.x * blockDim.x + threadIdx.x) >> 5;
    if (w >= NNODES) return;
    int lane = threadIdx.x & 31;
    bool active = lane < 10;

    int start = g_rowstart[w];
    int end   = g_rowstart[w + 1];

    const float4* __restrict__ h = (const float4*)g_h2;
    float4 acc = make_float4(0.f, 0.f, 0.f, 0.f);

    int j = start;
    for (; j + 1 < end; j += 2) {
        int   s0 = __ldg(&g_csr_src[j]);
        int   s1 = __ldg(&g_csr_src[j + 1]);
        float n0 = __ldg(&g_csr_nrm[j]);
        float n1 = __ldg(&g_csr_nrm[j + 1]);
        if (active) {
            float4 v0 = h[(size_t)s0 * 10 + lane];
            float4 v1 = h[(size_t)s1 * 10 + lane];
            acc.x = fmaf(n0, v0.x, acc.x); acc.y = fmaf(n0, v0.y, acc.y);
            acc.z = fmaf(n0, v0.z, acc.z); acc.w = fmaf(n0, v0.w, acc.w);
            acc.x = fmaf(n1, v1.x, acc.x); acc.y = fmaf(n1, v1.y, acc.y);
            acc.z = fmaf(n1, v1.z, acc.z); acc.w = fmaf(n1, v1.w, acc.w);
        }
    }
    if (j < end) {
        int   s0 = __ldg(&g_csr_src[j]);
        float n0 = __ldg(&g_csr_nrm[j]);
        if (active) {
            float4 v0 = h[(size_t)s0 * 10 + lane];
            acc.x = fmaf(n0, v0.x, acc.x); acc.y = fmaf(n0, v0.y, acc.y);
            acc.z = fmaf(n0, v0.z, acc.z); acc.w = fmaf(n0, v0.w, acc.w);
        }
    }

    if (active) {
        float di = g_dinv[w];
        float d2 = di * di;
        float4 hv = h[(size_t)w * 10 + lane];
        float4 bb = ((const float4*)b2)[lane];
        float4 r;
        r.x = fmaf(hv.x, d2, acc.x) + bb.x;
        r.y = fmaf(hv.y, d2, acc.y) + bb.y;
        r.z = fmaf(hv.z, d2, acc.z) + bb.z;
        r.w = fmaf(hv.w, d2, acc.w) + bb.w;
        ((float4*)out)[(size_t)w * 10 + lane] = r;
    }
}

// -----------------------------------------------------------------------------
extern "C" void kernel_launch(void* const* d_in, const int* in_sizes, int n_in,
                              void* d_out, int out_size) {
    const float* x   = (const float*)d_in[0];
    const int*   ei  = (const int*)  d_in[1];
    const float* W1  = (const float*)d_in[2];
    const float* b1  = (const float*)d_in[3];
    const float* W2  = (const float*)d_in[4];
    const float* b2  = (const float*)d_in[5];
    float* out = (float*)d_out;

    int*   degi_p; cudaGetSymbolAddress((void**)&degi_p, g_degi);
    float* h1_p;   cudaGetSymbolAddress((void**)&h1_p,   g_h1);
    float* h1b_p;  cudaGetSymbolAddress((void**)&h1b_p,  g_h1b);
    float* h2_p;   cudaGetSymbolAddress((void**)&h2_p,   g_h2);

    // ---- CSR build (overlapped logically with gemm1; sequential stream) ----
    zeroi_kernel<<<(NNODES + 255) / 256, 256>>>(degi_p, NNODES);
    degree_kernel<<<(NEDGES + 255) / 256, 256>>>(ei);
    dinv_kernel<<<(NNODES + 255) / 256, 256>>>();
    scan_kernel<<<1, 1024>>>();
    csrfill_kernel<<<(NEDGES + 255) / 256, 256>>>(ei);

    // ---- layer 1 ----
    gemm128_kernel<<<(NNODES + 127) / 128, 256>>>(x, W1, h1_p, NNODES);
    gather128_kernel<<<(NNODES * 32 + 255) / 256, 256>>>(b1);

    // ---- layer 2 ----
    gemm40_kernel<<<(NNODES + 127) / 128, 160>>>(h1b_p, W2, h2_p, NNODES);
    gather40_kernel<<<(NNODES * 32 + 255) / 256, 256>>>(b2, out);
}

// round 3
// speedup vs baseline: 1.4693x; 1.4693x over previous
#include <cuda_runtime.h>
#include <cuda_bf16.h>

#define NNODES 50000
#define NEDGES 600000
#define C_IN   128
#define C_HID  128
#define C_OUT  40
#define NB     ((NNODES + 255) / 256)   /* 196 scan blocks */

// ---------------- scratch (static device globals; no allocation) -------------
__device__ float g_h1  [NNODES * C_HID];   // x@W1
__device__ float g_h1b [NNODES * C_HID];   // layer-1 output (post relu)
__device__ float g_h2  [NNODES * C_OUT];   // h1b@W2
__device__ float g_dinv[NNODES];
__device__ int   g_degi[NNODES];           // in-degree (excl self loop)
__device__ int   g_locpre[NNODES];         // block-local exclusive prefix
__device__ int   g_blocksum[NB];
__device__ int   g_blockoff[NB];
__device__ int   g_rowstart[NNODES + 1];
__device__ int   g_cursor[NNODES];
__device__ int   g_csr_src[NEDGES];
__device__ float g_csr_nrm[NEDGES];

// ---------------- zero int buffer --------------------------------------------
__global__ void zeroi_kernel(int* p, int n) {
    int i = blockIdx.x * blockDim.x + threadIdx.x;
    if (i < n) p[i] = 0;
}

// ---------------- degree ------------------------------------------------------
__global__ void degree_kernel(const int* __restrict__ ei) {
    int e = blockIdx.x * blockDim.x + threadIdx.x;
    if (e < NEDGES) atomicAdd(&g_degi[ei[NEDGES + e]], 1);
}

// ---------------- scan phase A: block-local scan + dinv -----------------------
__global__ __launch_bounds__(256) void scanA_kernel() {
    __shared__ int s[256];
    int t   = threadIdx.x;
    int gid = blockIdx.x * 256 + t;
    int d   = (gid < NNODES) ? g_degi[gid] : 0;
    if (gid < NNODES) g_dinv[gid] = rsqrtf((float)d + 1.0f);
    s[t] = d;
    __syncthreads();
#pragma unroll
    for (int off = 1; off < 256; off <<= 1) {
        int v = (t >= off) ? s[t - off] : 0;
        __syncthreads();
        if (t >= off) s[t] += v;
        __syncthreads();
    }
    if (gid < NNODES) g_locpre[gid] = s[t] - d;   // exclusive
    if (t == 255) g_blocksum[blockIdx.x] = s[255];
}

// ---------------- scan phase B: scan block sums (1 block) ---------------------
__global__ __launch_bounds__(256) void scanB_kernel() {
    __shared__ int s[256];
    int t = threadIdx.x;
    int v = (t < NB) ? g_blocksum[t] : 0;
    s[t] = v;
    __syncthreads();
#pragma unroll
    for (int off = 1; off < 256; off <<= 1) {
        int u = (t >= off) ? s[t - off] : 0;
        __syncthreads();
        if (t >= off) s[t] += u;
        __syncthreads();
    }
    if (t < NB) g_blockoff[t] = s[t] - v;   // exclusive
}

// ---------------- scan phase C: apply offsets ---------------------------------
__global__ __launch_bounds__(256) void scanC_kernel() {
    int gid = blockIdx.x * 256 + threadIdx.x;
    if (gid < NNODES) {
        int r = g_locpre[gid] + g_blockoff[blockIdx.x];
        g_rowstart[gid] = r;
        g_cursor[gid]   = r;
    }
    if (gid == 0) g_rowstart[NNODES] = NEDGES;
}

// ---------------- CSR fill: bucket edges by dst, precompute norms ------------
__global__ void csrfill_kernel(const int* __restrict__ ei) {
    int e = blockIdx.x * blockDim.x + threadIdx.x;
    if (e >= NEDGES) return;
    int s = ei[e];
    int d = ei[NEDGES + e];
    int pos = atomicAdd(&g_cursor[d], 1);
    g_csr_src[pos] = s;
    g_csr_nrm[pos] = g_dinv[s] * g_dinv[d];
}

// ---------------- GEMM: [M,128] @ [128,128] -> [M,128] -----------------------
__global__ __launch_bounds__(256) void gemm128_kernel(
    const float* __restrict__ A, const float* __restrict__ W,
    float* __restrict__ C, int M)
{
    __shared__ float xs[16][132];
    __shared__ float ws[16][128];

    int tid = threadIdx.x;
    int tx = tid & 15;
    int ty = tid >> 4;
    int r0 = blockIdx.x * 128;

    float acc[8][8];
#pragma unroll
    for (int i = 0; i < 8; i++)
#pragma unroll
        for (int j = 0; j < 8; j++) acc[i][j] = 0.f;

    for (int k0 = 0; k0 < 128; k0 += 16) {
#pragma unroll
        for (int L = tid; L < 512; L += 256) {
            int r  = L >> 2;
            int kg = L & 3;
            float4 v = make_float4(0.f, 0.f, 0.f, 0.f);
            int row = r0 + r;
            if (row < M)
                v = *(const float4*)&A[(size_t)row * 128 + k0 + kg * 4];
            xs[kg * 4 + 0][r] = v.x;
            xs[kg * 4 + 1][r] = v.y;
            xs[kg * 4 + 2][r] = v.z;
            xs[kg * 4 + 3][r] = v.w;
        }
#pragma unroll
        for (int L = tid; L < 512; L += 256) {
            int k  = L >> 5;
            int cg = L & 31;
            *(float4*)&ws[k][cg * 4] =
                *(const float4*)&W[(size_t)(k0 + k) * 128 + cg * 4];
        }
        __syncthreads();

#pragma unroll
        for (int k = 0; k < 16; ++k) {
            float a[8], b[8];
            *(float4*)(a)     = *(const float4*)&xs[k][ty * 8];
            *(float4*)(a + 4) = *(const float4*)&xs[k][ty * 8 + 4];
            *(float4*)(b)     = *(const float4*)&ws[k][tx * 8];
            *(float4*)(b + 4) = *(const float4*)&ws[k][tx * 8 + 4];
#pragma unroll
            for (int i = 0; i < 8; i++)
#pragma unroll
                for (int j = 0; j < 8; j++)
                    acc[i][j] = fmaf(a[i], b[j], acc[i][j]);
        }
        __syncthreads();
    }

#pragma unroll
    for (int i = 0; i < 8; i++) {
        int row = r0 + ty * 8 + i;
        if (row < M) {
            *(float4*)&C[(size_t)row * 128 + tx * 8] =
                make_float4(acc[i][0], acc[i][1], acc[i][2], acc[i][3]);
            *(float4*)&C[(size_t)row * 128 + tx * 8 + 4] =
                make_float4(acc[i][4], acc[i][5], acc[i][6], acc[i][7]);
        }
    }
}

// ---------------- GEMM: [M,128] @ [128,40] -> [M,40] -------------------------
__global__ __launch_bounds__(160) void gemm40_kernel(
    const float* __restrict__ A, const float* __restrict__ W,
    float* __restrict__ C, int M)
{
    __shared__ float xs[16][132];
    __shared__ float ws[16][40];

    int tid = threadIdx.x;
    int tx = tid % 10;
    int ty = tid / 10;
    int r0 = blockIdx.x * 128;

    float acc[8][4];
#pragma unroll
    for (int i = 0; i < 8; i++)
#pragma unroll
        for (int j = 0; j < 4; j++) acc[i][j] = 0.f;

    for (int k0 = 0; k0 < 128; k0 += 16) {
        for (int L = tid; L < 512; L += 160) {
            int r  = L >> 2;
            int kg = L & 3;
            float4 v = make_float4(0.f, 0.f, 0.f, 0.f);
            int row = r0 + r;
            if (row < M)
                v = *(const float4*)&A[(size_t)row * 128 + k0 + kg * 4];
            xs[kg * 4 + 0][r] = v.x;
            xs[kg * 4 + 1][r] = v.y;
            xs[kg * 4 + 2][r] = v.z;
            xs[kg * 4 + 3][r] = v.w;
        }
        {
            int L = tid;
            int k  = L / 10;
            int cg = L % 10;
            *(float4*)&ws[k][cg * 4] =
                *(const float4*)&W[(size_t)(k0 + k) * 40 + cg * 4];
        }
        __syncthreads();

#pragma unroll
        for (int k = 0; k < 16; ++k) {
            float a[8], b[4];
            *(float4*)(a)     = *(const float4*)&xs[k][ty * 8];
            *(float4*)(a + 4) = *(const float4*)&xs[k][ty * 8 + 4];
            *(float4*)(b)     = *(const float4*)&ws[k][tx * 4];
#pragma unroll
            for (int i = 0; i < 8; i++)
#pragma unroll
                for (int j = 0; j < 4; j++)
                    acc[i][j] = fmaf(a[i], b[j], acc[i][j]);
        }
        __syncthreads();
    }

#pragma unroll
    for (int i = 0; i < 8; i++) {
        int row = r0 + ty * 8 + i;
        if (row < M) {
            *(float4*)&C[(size_t)row * 40 + tx * 4] =
                make_float4(acc[i][0], acc[i][1], acc[i][2], acc[i][3]);
        }
    }
}

// ---------------- gather layer 1 (C=128): warp per node ----------------------
__global__ __launch_bounds__(256) void gather128_kernel(const float* __restrict__ b1) {
    int w = (blockIdx.x * blockDim.x + threadIdx.x) >> 5;
    if (w >= NNODES) return;
    int lane = threadIdx.x & 31;

    int start = g_rowstart[w];
    int end   = g_rowstart[w + 1];

    const float4* __restrict__ h = (const float4*)g_h1;
    float4 acc = make_float4(0.f, 0.f, 0.f, 0.f);

    int j = start;
    for (; j + 1 < end; j += 2) {
        int   s0 = __ldg(&g_csr_src[j]);
        int   s1 = __ldg(&g_csr_src[j + 1]);
        float n0 = __ldg(&g_csr_nrm[j]);
        float n1 = __ldg(&g_csr_nrm[j + 1]);
        float4 v0 = h[(size_t)s0 * 32 + lane];
        float4 v1 = h[(size_t)s1 * 32 + lane];
        acc.x = fmaf(n0, v0.x, acc.x); acc.y = fmaf(n0, v0.y, acc.y);
        acc.z = fmaf(n0, v0.z, acc.z); acc.w = fmaf(n0, v0.w, acc.w);
        acc.x = fmaf(n1, v1.x, acc.x); acc.y = fmaf(n1, v1.y, acc.y);
        acc.z = fmaf(n1, v1.z, acc.z); acc.w = fmaf(n1, v1.w, acc.w);
    }
    if (j < end) {
        int   s0 = __ldg(&g_csr_src[j]);
        float n0 = __ldg(&g_csr_nrm[j]);
        float4 v0 = h[(size_t)s0 * 32 + lane];
        acc.x = fmaf(n0, v0.x, acc.x); acc.y = fmaf(n0, v0.y, acc.y);
        acc.z = fmaf(n0, v0.z, acc.z); acc.w = fmaf(n0, v0.w, acc.w);
    }

    float di = g_dinv[w];
    float d2 = di * di;
    float4 hv = h[(size_t)w * 32 + lane];
    float4 bb = ((const float4*)b1)[lane];
    float4 r;
    r.x = fmaxf(fmaf(hv.x, d2, acc.x) + bb.x, 0.f);
    r.y = fmaxf(fmaf(hv.y, d2, acc.y) + bb.y, 0.f);
    r.z = fmaxf(fmaf(hv.z, d2, acc.z) + bb.z, 0.f);
    r.w = fmaxf(fmaf(hv.w, d2, acc.w) + bb.w, 0.f);
    ((float4*)g_h1b)[(size_t)w * 32 + lane] = r;
}

// ---------------- gather layer 2 (C=40): warp per node, lanes 0-9 -----------
__global__ __launch_bounds__(256) void gather40_kernel(const float* __restrict__ b2,
                                                       float* __restrict__ out) {
    int w = (blockIdx.x * blockDim.x + threadIdx.x) >> 5;
    if (w >= NNODES) return;
    int lane = threadIdx.x & 31;
    bool active = lane < 10;

    int start = g_rowstart[w];
    int end   = g_rowstart[w + 1];

    const float4* __restrict__ h = (const float4*)g_h2;
    float4 acc = make_float4(0.f, 0.f, 0.f, 0.f);

    int j = start;
    for (; j + 1 < end; j += 2) {
        int   s0 = __ldg(&g_csr_src[j]);
        int   s1 = __ldg(&g_csr_src[j + 1]);
        float n0 = __ldg(&g_csr_nrm[j]);
        float n1 = __ldg(&g_csr_nrm[j + 1]);
        if (active) {
            float4 v0 = h[(size_t)s0 * 10 + lane];
            float4 v1 = h[(size_t)s1 * 10 + lane];
            acc.x = fmaf(n0, v0.x, acc.x); acc.y = fmaf(n0, v0.y, acc.y);
            acc.z = fmaf(n0, v0.z, acc.z); acc.w = fmaf(n0, v0.w, acc.w);
            acc.x = fmaf(n1, v1.x, acc.x); acc.y = fmaf(n1, v1.y, acc.y);
            acc.z = fmaf(n1, v1.z, acc.z); acc.w = fmaf(n1, v1.w, acc.w);
        }
    }
    if (j < end) {
        int   s0 = __ldg(&g_csr_src[j]);
        float n0 = __ldg(&g_csr_nrm[j]);
        if (active) {
            float4 v0 = h[(size_t)s0 * 10 + lane];
            acc.x = fmaf(n0, v0.x, acc.x); acc.y = fmaf(n0, v0.y, acc.y);
            acc.z = fmaf(n0, v0.z, acc.z); acc.w = fmaf(n0, v0.w, acc.w);
        }
    }

    if (active) {
        float di = g_dinv[w];
        float d2 = di * di;
        float4 hv = h[(size_t)w * 10 + lane];
        float4 bb = ((const float4*)b2)[lane];
        float4 r;
        r.x = fmaf(hv.x, d2, acc.x) + bb.x;
        r.y = fmaf(hv.y, d2, acc.y) + bb.y;
        r.z = fmaf(hv.z, d2, acc.z) + bb.z;
        r.w = fmaf(hv.w, d2, acc.w) + bb.w;
        ((float4*)out)[(size_t)w * 10 + lane] = r;
    }
}

// -----------------------------------------------------------------------------
extern "C" void kernel_launch(void* const* d_in, const int* in_sizes, int n_in,
                              void* d_out, int out_size) {
    const float* x   = (const float*)d_in[0];
    const int*   ei  = (const int*)  d_in[1];
    const float* W1  = (const float*)d_in[2];
    const float* b1  = (const float*)d_in[3];
    const float* W2  = (const float*)d_in[4];
    const float* b2  = (const float*)d_in[5];
    float* out = (float*)d_out;

    int*   degi_p; cudaGetSymbolAddress((void**)&degi_p, g_degi);
    float* h1_p;   cudaGetSymbolAddress((void**)&h1_p,   g_h1);
    float* h1b_p;  cudaGetSymbolAddress((void**)&h1b_p,  g_h1b);
    float* h2_p;   cudaGetSymbolAddress((void**)&h2_p,   g_h2);

    // ---- CSR build ----
    zeroi_kernel<<<(NNODES + 255) / 256, 256>>>(degi_p, NNODES);
    degree_kernel<<<(NEDGES + 255) / 256, 256>>>(ei);
    scanA_kernel<<<NB, 256>>>();
    scanB_kernel<<<1, 256>>>();
    scanC_kernel<<<NB, 256>>>();
    csrfill_kernel<<<(NEDGES + 255) / 256, 256>>>(ei);

    // ---- layer 1 ----
    gemm128_kernel<<<(NNODES + 127) / 128, 256>>>(x, W1, h1_p, NNODES);
    gather128_kernel<<<(NNODES * 32 + 255) / 256, 256>>>(b1);

    // ---- layer 2 ----
    gemm40_kernel<<<(NNODES + 127) / 128, 160>>>(h1b_p, W2, h2_p, NNODES);
    gather40_kernel<<<(NNODES * 32 + 255) / 256, 256>>>(b2, out);
}

// round 4
// speedup vs baseline: 2.0913x; 1.4234x over previous
#include <cuda_runtime.h>
#include <cuda_bf16.h>
#include <cstdint>

#define NNODES 50000
#define NEDGES 600000
#define C_IN   128
#define C_HID  128
#define C_OUT  40
#define NB     ((NNODES + 255) / 256)   /* 196 scan blocks */
#define KS     136                       /* smem k-major stride (conflict-free) */

// ---------------- scratch (static device globals; no allocation) -------------
__device__ float g_h1  [NNODES * C_HID];   // x@W1
__device__ float g_h1b [NNODES * C_HID];   // layer-1 output (post relu)
__device__ float g_h2  [NNODES * C_OUT];   // h1b@W2
__device__ float g_dinv[NNODES];
__device__ int   g_degi[NNODES];
__device__ int   g_locpre[NNODES];
__device__ int   g_blocksum[NB];
__device__ int   g_blockoff[NB];
__device__ int   g_rowstart[NNODES + 1];
__device__ int   g_cursor[NNODES];
__device__ int   g_csr_src[NEDGES];
__device__ float g_csr_nrm[NEDGES];

// ---------------- tf32 helpers -----------------------------------------------
__device__ __forceinline__ uint32_t f2tf32(float f) {
    uint32_t u;
    asm("cvt.rna.tf32.f32 %0, %1;" : "=r"(u) : "f"(f));
    return u;
}
__device__ __forceinline__ void mma_tf32(
    float& d0, float& d1, float& d2, float& d3,
    uint32_t a0, uint32_t a1, uint32_t a2, uint32_t a3,
    uint32_t b0, uint32_t b1)
{
    asm volatile(
        "mma.sync.aligned.m16n8k8.row.col.f32.tf32.tf32.f32 "
        "{%0,%1,%2,%3}, {%4,%5,%6,%7}, {%8,%9}, {%0,%1,%2,%3};"
        : "+f"(d0), "+f"(d1), "+f"(d2), "+f"(d3)
        : "r"(a0), "r"(a1), "r"(a2), "r"(a3), "r"(b0), "r"(b1));
}

// ---------------- zero int buffer --------------------------------------------
__global__ void zeroi_kernel(int* p, int n) {
    int i = blockIdx.x * blockDim.x + threadIdx.x;
    if (i < n) p[i] = 0;
}

// ---------------- degree ------------------------------------------------------
__global__ void degree_kernel(const int* __restrict__ ei) {
    int e = blockIdx.x * blockDim.x + threadIdx.x;
    if (e < NEDGES) atomicAdd(&g_degi[ei[NEDGES + e]], 1);
}

// ---------------- scan phase A: block-local scan + dinv -----------------------
__global__ __launch_bounds__(256) void scanA_kernel() {
    __shared__ int s[256];
    int t   = threadIdx.x;
    int gid = blockIdx.x * 256 + t;
    int d   = (gid < NNODES) ? g_degi[gid] : 0;
    if (gid < NNODES) g_dinv[gid] = rsqrtf((float)d + 1.0f);
    s[t] = d;
    __syncthreads();
#pragma unroll
    for (int off = 1; off < 256; off <<= 1) {
        int v = (t >= off) ? s[t - off] : 0;
        __syncthreads();
        if (t >= off) s[t] += v;
        __syncthreads();
    }
    if (gid < NNODES) g_locpre[gid] = s[t] - d;
    if (t == 255) g_blocksum[blockIdx.x] = s[255];
}

// ---------------- scan phase B -------------------------------------------------
__global__ __launch_bounds__(256) void scanB_kernel() {
    __shared__ int s[256];
    int t = threadIdx.x;
    int v = (t < NB) ? g_blocksum[t] : 0;
    s[t] = v;
    __syncthreads();
#pragma unroll
    for (int off = 1; off < 256; off <<= 1) {
        int u = (t >= off) ? s[t - off] : 0;
        __syncthreads();
        if (t >= off) s[t] += u;
        __syncthreads();
    }
    if (t < NB) g_blockoff[t] = s[t] - v;
}

// ---------------- scan phase C -------------------------------------------------
__global__ __launch_bounds__(256) void scanC_kernel() {
    int gid = blockIdx.x * 256 + threadIdx.x;
    if (gid < NNODES) {
        int r = g_locpre[gid] + g_blockoff[blockIdx.x];
        g_rowstart[gid] = r;
        g_cursor[gid]   = r;
    }
    if (gid == 0) g_rowstart[NNODES] = NEDGES;
}

// ---------------- CSR fill ------------------------------------------------------
__global__ void csrfill_kernel(const int* __restrict__ ei) {
    int e = blockIdx.x * blockDim.x + threadIdx.x;
    if (e >= NEDGES) return;
    int s = ei[e];
    int d = ei[NEDGES + e];
    int pos = atomicAdd(&g_cursor[d], 1);
    g_csr_src[pos] = s;
    g_csr_nrm[pos] = g_dinv[s] * g_dinv[d];
}

// ---------------- tf32 GEMM: [M,128] @ [128,128] -> [M,128] --------------------
// Block tile 128x128, 8 warps (16 rows each), K-tile 32, m16n8k8 MMA.
__global__ __launch_bounds__(256) void gemm128_tf32_kernel(
    const float* __restrict__ A, const float* __restrict__ W,
    float* __restrict__ C, int M)
{
    __shared__ uint32_t xs[32 * KS];   // [k][row]  tf32 bits
    __shared__ uint32_t ws[32 * KS];   // [k][col]  tf32 bits

    int tid  = threadIdx.x;
    int w    = tid >> 5;
    int lane = tid & 31;
    int g    = lane >> 2;
    int t4   = lane & 3;
    int r0   = blockIdx.x * 128;

    float acc[16][4];
#pragma unroll
    for (int j = 0; j < 16; j++)
#pragma unroll
        for (int i = 0; i < 4; i++) acc[j][i] = 0.f;

    for (int k0 = 0; k0 < 128; k0 += 32) {
        // x tile: 128 rows x 32 k -> transpose to k-major
#pragma unroll
        for (int L = tid; L < 1024; L += 256) {
            int r  = L >> 3;
            int kg = L & 7;
            int row = r0 + r;
            float4 v = make_float4(0.f, 0.f, 0.f, 0.f);
            if (row < M)
                v = *(const float4*)&A[(size_t)row * 128 + k0 + kg * 4];
            xs[(kg * 4 + 0) * KS + r] = f2tf32(v.x);
            xs[(kg * 4 + 1) * KS + r] = f2tf32(v.y);
            xs[(kg * 4 + 2) * KS + r] = f2tf32(v.z);
            xs[(kg * 4 + 3) * KS + r] = f2tf32(v.w);
        }
        // W tile: 32 k x 128 n (already k-major)
#pragma unroll
        for (int L = tid; L < 1024; L += 256) {
            int k  = L >> 5;
            int cg = L & 31;
            float4 v = *(const float4*)&W[(size_t)(k0 + k) * 128 + cg * 4];
            uint32_t* p = &ws[k * KS + cg * 4];
            p[0] = f2tf32(v.x);
            p[1] = f2tf32(v.y);
            p[2] = f2tf32(v.z);
            p[3] = f2tf32(v.w);
        }
        __syncthreads();

#pragma unroll
        for (int kt = 0; kt < 4; kt++) {
            int kr = kt * 8 + t4;
            uint32_t a0 = xs[kr * KS       + w * 16 + g];
            uint32_t a1 = xs[kr * KS       + w * 16 + g + 8];
            uint32_t a2 = xs[(kr + 4) * KS + w * 16 + g];
            uint32_t a3 = xs[(kr + 4) * KS + w * 16 + g + 8];
#pragma unroll
            for (int j = 0; j < 16; j++) {
                uint32_t b0 = ws[kr * KS       + j * 8 + g];
                uint32_t b1 = ws[(kr + 4) * KS + j * 8 + g];
                mma_tf32(acc[j][0], acc[j][1], acc[j][2], acc[j][3],
                         a0, a1, a2, a3, b0, b1);
            }
        }
        __syncthreads();
    }

    int rowA = r0 + w * 16 + g;
#pragma unroll
    for (int j = 0; j < 16; j++) {
        if (rowA < M)
            *(float2*)&C[(size_t)rowA * 128 + j * 8 + t4 * 2] =
                make_float2(acc[j][0], acc[j][1]);
        if (rowA + 8 < M)
            *(float2*)&C[(size_t)(rowA + 8) * 128 + j * 8 + t4 * 2] =
                make_float2(acc[j][2], acc[j][3]);
    }
}

// ---------------- tf32 GEMM: [M,128] @ [128,40] -> [M,40] ----------------------
__global__ __launch_bounds__(256) void gemm40_tf32_kernel(
    const float* __restrict__ A, const float* __restrict__ W,
    float* __restrict__ C, int M)
{
    __shared__ uint32_t xs[32 * KS];
    __shared__ uint32_t ws[32 * KS];

    int tid  = threadIdx.x;
    int w    = tid >> 5;
    int lane = tid & 31;
    int g    = lane >> 2;
    int t4   = lane & 3;
    int r0   = blockIdx.x * 128;

    float acc[5][4];
#pragma unroll
    for (int j = 0; j < 5; j++)
#pragma unroll
        for (int i = 0; i < 4; i++) acc[j][i] = 0.f;

    for (int k0 = 0; k0 < 128; k0 += 32) {
#pragma unroll
        for (int L = tid; L < 1024; L += 256) {
            int r  = L >> 3;
            int kg = L & 7;
            int row = r0 + r;
            float4 v = make_float4(0.f, 0.f, 0.f, 0.f);
            if (row < M)
                v = *(const float4*)&A[(size_t)row * 128 + k0 + kg * 4];
            xs[(kg * 4 + 0) * KS + r] = f2tf32(v.x);
            xs[(kg * 4 + 1) * KS + r] = f2tf32(v.y);
            xs[(kg * 4 + 2) * KS + r] = f2tf32(v.z);
            xs[(kg * 4 + 3) * KS + r] = f2tf32(v.w);
        }
        // W tile: 32 k x 40 n -> 320 float4 loads
        for (int L = tid; L < 320; L += 256) {
            int k  = L / 10;
            int cg = L % 10;
            float4 v = *(const float4*)&W[(size_t)(k0 + k) * 40 + cg * 4];
            uint32_t* p = &ws[k * KS + cg * 4];
            p[0] = f2tf32(v.x);
            p[1] = f2tf32(v.y);
            p[2] = f2tf32(v.z);
            p[3] = f2tf32(v.w);
        }
        __syncthreads();

#pragma unroll
        for (int kt = 0; kt < 4; kt++) {
            int kr = kt * 8 + t4;
            uint32_t a0 = xs[kr * KS       + w * 16 + g];
            uint32_t a1 = xs[kr * KS       + w * 16 + g + 8];
            uint32_t a2 = xs[(kr + 4) * KS + w * 16 + g];
            uint32_t a3 = xs[(kr + 4) * KS + w * 16 + g + 8];
#pragma unroll
            for (int j = 0; j < 5; j++) {
                uint32_t b0 = ws[kr * KS       + j * 8 + g];
                uint32_t b1 = ws[(kr + 4) * KS + j * 8 + g];
                mma_tf32(acc[j][0], acc[j][1], acc[j][2], acc[j][3],
                         a0, a1, a2, a3, b0, b1);
            }
        }
        __syncthreads();
    }

    int rowA = r0 + w * 16 + g;
#pragma unroll
    for (int j = 0; j < 5; j++) {
        if (rowA < M)
            *(float2*)&C[(size_t)rowA * 40 + j * 8 + t4 * 2] =
                make_float2(acc[j][0], acc[j][1]);
        if (rowA + 8 < M)
            *(float2*)&C[(size_t)(rowA + 8) * 40 + j * 8 + t4 * 2] =
                make_float2(acc[j][2], acc[j][3]);
    }
}

// ---------------- gather layer 1 (C=128): warp per node ----------------------
__global__ __launch_bounds__(256) void gather128_kernel(const float* __restrict__ b1) {
    int w = (blockIdx.x * blockDim.x + threadIdx.x) >> 5;
    if (w >= NNODES) return;
    int lane = threadIdx.x & 31;

    int start = g_rowstart[w];
    int end   = g_rowstart[w + 1];

    const float4* __restrict__ h = (const float4*)g_h1;
    float4 acc = make_float4(0.f, 0.f, 0.f, 0.f);

    int j = start;
    for (; j + 1 < end; j += 2) {
        int   s0 = __ldg(&g_csr_src[j]);
        int   s1 = __ldg(&g_csr_src[j + 1]);
        float n0 = __ldg(&g_csr_nrm[j]);
        float n1 = __ldg(&g_csr_nrm[j + 1]);
        float4 v0 = h[(size_t)s0 * 32 + lane];
        float4 v1 = h[(size_t)s1 * 32 + lane];
        acc.x = fmaf(n0, v0.x, acc.x); acc.y = fmaf(n0, v0.y, acc.y);
        acc.z = fmaf(n0, v0.z, acc.z); acc.w = fmaf(n0, v0.w, acc.w);
        acc.x = fmaf(n1, v1.x, acc.x); acc.y = fmaf(n1, v1.y, acc.y);
        acc.z = fmaf(n1, v1.z, acc.z); acc.w = fmaf(n1, v1.w, acc.w);
    }
    if (j < end) {
        int   s0 = __ldg(&g_csr_src[j]);
        float n0 = __ldg(&g_csr_nrm[j]);
        float4 v0 = h[(size_t)s0 * 32 + lane];
        acc.x = fmaf(n0, v0.x, acc.x); acc.y = fmaf(n0, v0.y, acc.y);
        acc.z = fmaf(n0, v0.z, acc.z); acc.w = fmaf(n0, v0.w, acc.w);
    }

    float di = g_dinv[w];
    float d2 = di * di;
    float4 hv = h[(size_t)w * 32 + lane];
    float4 bb = ((const float4*)b1)[lane];
    float4 r;
    r.x = fmaxf(fmaf(hv.x, d2, acc.x) + bb.x, 0.f);
    r.y = fmaxf(fmaf(hv.y, d2, acc.y) + bb.y, 0.f);
    r.z = fmaxf(fmaf(hv.z, d2, acc.z) + bb.z, 0.f);
    r.w = fmaxf(fmaf(hv.w, d2, acc.w) + bb.w, 0.f);
    ((float4*)g_h1b)[(size_t)w * 32 + lane] = r;
}

// ---------------- gather layer 2 (C=40): TWO nodes per warp ------------------
__global__ __launch_bounds__(256) void gather40_kernel(const float* __restrict__ b2,
                                                       float* __restrict__ out) {
    int w = (blockIdx.x * blockDim.x + threadIdx.x) >> 5;
    int lane = threadIdx.x & 31;
    int node = w * 2 + (lane >> 4);
    if (node >= NNODES) return;
    int sub = lane & 15;
    bool active = sub < 10;

    int start = g_rowstart[node];
    int end   = g_rowstart[node + 1];

    const float4* __restrict__ h = (const float4*)g_h2;
    float4 acc = make_float4(0.f, 0.f, 0.f, 0.f);

    int j = start;
    for (; j + 1 < end; j += 2) {
        int   s0 = __ldg(&g_csr_src[j]);
        int   s1 = __ldg(&g_csr_src[j + 1]);
        float n0 = __ldg(&g_csr_nrm[j]);
        float n1 = __ldg(&g_csr_nrm[j + 1]);
        if (active) {
            float4 v0 = h[(size_t)s0 * 10 + sub];
            float4 v1 = h[(size_t)s1 * 10 + sub];
            acc.x = fmaf(n0, v0.x, acc.x); acc.y = fmaf(n0, v0.y, acc.y);
            acc.z = fmaf(n0, v0.z, acc.z); acc.w = fmaf(n0, v0.w, acc.w);
            acc.x = fmaf(n1, v1.x, acc.x); acc.y = fmaf(n1, v1.y, acc.y);
            acc.z = fmaf(n1, v1.z, acc.z); acc.w = fmaf(n1, v1.w, acc.w);
        }
    }
    if (j < end) {
        int   s0 = __ldg(&g_csr_src[j]);
        float n0 = __ldg(&g_csr_nrm[j]);
        if (active) {
            float4 v0 = h[(size_t)s0 * 10 + sub];
            acc.x = fmaf(n0, v0.x, acc.x); acc.y = fmaf(n0, v0.y, acc.y);
            acc.z = fmaf(n0, v0.z, acc.z); acc.w = fmaf(n0, v0.w, acc.w);
        }
    }

    if (active) {
        float di = g_dinv[node];
        float d2 = di * di;
        float4 hv = h[(size_t)node * 10 + sub];
        float4 bb = ((const float4*)b2)[sub];
        float4 r;
        r.x = fmaf(hv.x, d2, acc.x) + bb.x;
        r.y = fmaf(hv.y, d2, acc.y) + bb.y;
        r.z = fmaf(hv.z, d2, acc.z) + bb.z;
        r.w = fmaf(hv.w, d2, acc.w) + bb.w;
        ((float4*)out)[(size_t)node * 10 + sub] = r;
    }
}

// -----------------------------------------------------------------------------
extern "C" void kernel_launch(void* const* d_in, const int* in_sizes, int n_in,
                              void* d_out, int out_size) {
    const float* x   = (const float*)d_in[0];
    const int*   ei  = (const int*)  d_in[1];
    const float* W1  = (const float*)d_in[2];
    const float* b1  = (const float*)d_in[3];
    const float* W2  = (const float*)d_in[4];
    const float* b2  = (const float*)d_in[5];
    float* out = (float*)d_out;

    int*   degi_p; cudaGetSymbolAddress((void**)&degi_p, g_degi);
    float* h1_p;   cudaGetSymbolAddress((void**)&h1_p,   g_h1);
    float* h1b_p;  cudaGetSymbolAddress((void**)&h1b_p,  g_h1b);
    float* h2_p;   cudaGetSymbolAddress((void**)&h2_p,   g_h2);

    // ---- CSR build ----
    zeroi_kernel<<<(NNODES + 255) / 256, 256>>>(degi_p, NNODES);
    degree_kernel<<<(NEDGES + 255) / 256, 256>>>(ei);
    scanA_kernel<<<NB, 256>>>();
    scanB_kernel<<<1, 256>>>();
    scanC_kernel<<<NB, 256>>>();
    csrfill_kernel<<<(NEDGES + 255) / 256, 256>>>(ei);

    // ---- layer 1 ----
    gemm128_tf32_kernel<<<(NNODES + 127) / 128, 256>>>(x, W1, h1_p, NNODES);
    gather128_kernel<<<(NNODES * 32 + 255) / 256, 256>>>(b1);

    // ---- layer 2 ----
    gemm40_tf32_kernel<<<(NNODES + 127) / 128, 256>>>(h1b_p, W2, h2_p, NNODES);
    gather40_kernel<<<((NNODES + 1) / 2 * 32 + 255) / 256, 256>>>(b2, out);
}